// round 5
// baseline (speedup 1.0000x reference)
#include <cuda_runtime.h>
#include <cstdint>

// CRF token-classifier NLL, single fused kernel. B=64,S=512,H=768,L=3 -> scalar.
// cp.async double-buffered pipeline streams hidden into smem (bytes-in-flight
// decoupled from registers); emissions computed from smem; register-resident
// shfl log-semiring reduce; last-block epilogue.

#define Bn 64
#define Sn 512
#define Hn 768
#define CHUNK 64
#define NCH (Sn / CHUNK)    // 8
#define TS_TILE 4
#define NTILE (CHUNK / TS_TILE) // 16
#define T1 192              // 6 warps

// scratch (no allocations allowed)
__device__ float g_M[Bn][NCH][9];
__device__ float g_gold[Bn][NCH];
__device__ float g_alpha0[Bn][3];
__device__ int   g_last[Bn][NCH];
__device__ unsigned int g_ctr = 0;

__device__ __forceinline__ float lse3(float a, float b, float c) {
    float m = fmaxf(a, fmaxf(b, c));
    return m + __logf(__expf(a - m) + __expf(b - m) + __expf(c - m));
}

__device__ __forceinline__ void cpa16(float* dst, const float* src) {
    unsigned s = (unsigned)__cvta_generic_to_shared(dst);
    asm volatile("cp.async.cg.shared.global [%0], [%1], 16;" :: "r"(s), "l"(src));
}
__device__ __forceinline__ void cpa_commit() {
    asm volatile("cp.async.commit_group;" ::: "memory");
}

__global__ __launch_bounds__(T1, 5) void crf_fused(
    const float* __restrict__ hidden, const float* __restrict__ W,
    const float* __restrict__ bias, const float* __restrict__ start,
    const float* __restrict__ endt, const float* __restrict__ trans,
    const int* __restrict__ mask, const int* __restrict__ labels,
    float* __restrict__ out)
{
    const int chunk = blockIdx.x;
    const int batch = blockIdx.y;
    const int tid = threadIdx.x, lane = tid & 31, wid = tid >> 5;

    __shared__ float buf[2][TS_TILE * Hn];     // 24.6 KB stream buffers
    __shared__ float w0[Hn], w1[Hn], w2[Hn];   // W transposed (9.2 KB)
    __shared__ float em[CHUNK][4];             // emissions
    __shared__ float part[2][3][2][4];         // [tsp][cg][q][class]
    __shared__ float sbias[4];
    __shared__ float str[9];
    __shared__ float wprod[2][9];
    __shared__ float sgold[2];
    __shared__ int   slast[2];
    __shared__ int   s_is_last;
    __shared__ float sred[2];

    const float* hb = hidden + ((size_t)batch * Sn + (size_t)chunk * CHUNK) * Hn;

    // stage W (transposed), transitions, bias
    for (int i = tid; i < Hn; i += T1) {
        w0[i] = W[i * 3 + 0];
        w1[i] = W[i * 3 + 1];
        w2[i] = W[i * 3 + 2];
    }
    if (tid < 9) str[tid] = trans[tid];
    if (tid < 3) sbias[tid] = bias[tid];

    // prologue: prefetch tiles 0,1   (each tile: 768 x 16B ops, 4 per thread)
    #pragma unroll
    for (int i = 0; i < 4; i++) {
        int j = tid + T1 * i;
        cpa16(&buf[0][j * 4], hb + 0 * (TS_TILE * Hn) + j * 4);
    }
    cpa_commit();
    #pragma unroll
    for (int i = 0; i < 4; i++) {
        int j = tid + T1 * i;
        cpa16(&buf[1][j * 4], hb + 1 * (TS_TILE * Hn) + j * 4);
    }
    cpa_commit();

    // ---- main pipeline: 16 tiles of 4 timesteps
    const int tsp = wid & 1;       // ts-pair within tile: ts = 2*tsp + q
    const int cg  = wid >> 1;      // chunk group 0..2 -> chunks {2cg, 2cg+1}

    for (int t = 0; t < NTILE; t++) {
        if (t < NTILE - 1) asm volatile("cp.async.wait_group 1;" ::: "memory");
        else               asm volatile("cp.async.wait_group 0;" ::: "memory");
        __syncthreads();

        // compute emissions partials for this tile
        {
            const float* bp = buf[t & 1];
            float a00=0,a01=0,a02=0,a10=0,a11=0,a12=0;
            #pragma unroll
            for (int cc = 0; cc < 2; cc++) {
                const int e = 4 * lane + 128 * (2 * cg + cc);
                float4 v0 = *(const float4*)(w0 + e);
                float4 v1 = *(const float4*)(w1 + e);
                float4 v2 = *(const float4*)(w2 + e);
                float4 x0 = *(const float4*)(bp + (2 * tsp + 0) * Hn + e);
                float4 x1 = *(const float4*)(bp + (2 * tsp + 1) * Hn + e);
                a00 += x0.x*v0.x + x0.y*v0.y + x0.z*v0.z + x0.w*v0.w;
                a01 += x0.x*v1.x + x0.y*v1.y + x0.z*v1.z + x0.w*v1.w;
                a02 += x0.x*v2.x + x0.y*v2.y + x0.z*v2.z + x0.w*v2.w;
                a10 += x1.x*v0.x + x1.y*v0.y + x1.z*v0.z + x1.w*v0.w;
                a11 += x1.x*v1.x + x1.y*v1.y + x1.z*v1.z + x1.w*v1.w;
                a12 += x1.x*v2.x + x1.y*v2.y + x1.z*v2.z + x1.w*v2.w;
            }
            #pragma unroll
            for (int off = 16; off; off >>= 1) {
                a00 += __shfl_xor_sync(0xffffffffu, a00, off);
                a01 += __shfl_xor_sync(0xffffffffu, a01, off);
                a02 += __shfl_xor_sync(0xffffffffu, a02, off);
                a10 += __shfl_xor_sync(0xffffffffu, a10, off);
                a11 += __shfl_xor_sync(0xffffffffu, a11, off);
                a12 += __shfl_xor_sync(0xffffffffu, a12, off);
            }
            if (lane == 0) {
                part[tsp][cg][0][0] = a00; part[tsp][cg][0][1] = a01;
                part[tsp][cg][0][2] = a02;
                part[tsp][cg][1][0] = a10; part[tsp][cg][1][1] = a11;
                part[tsp][cg][1][2] = a12;
            }
        }
        __syncthreads();

        // prefetch tile t+2 into the buffer we just consumed
        if (t + 2 < NTILE) {
            #pragma unroll
            for (int i = 0; i < 4; i++) {
                int j = tid + T1 * i;
                cpa16(&buf[t & 1][j * 4], hb + (t + 2) * (TS_TILE * Hn) + j * 4);
            }
            cpa_commit();
        }

        // fold partials into em (safe: next part write is after next barrier)
        if (tid < 12) {
            const int ts = tid >> 2, j = tid & 3;   // ts 0..2? need 4 ts x 3 classes
        }
        if (tid < TS_TILE * 3) {
            const int ts = tid / 3, j = tid - ts * 3;
            em[t * TS_TILE + ts][j] =
                part[ts >> 1][0][ts & 1][j] + part[ts >> 1][1][ts & 1][j] +
                part[ts >> 1][2][ts & 1][j] + sbias[j];
        }
    }
    __syncthreads();

    // ---- per-step matrices (registers) + gold partial + last-mask index
    float gp = 0.0f;
    int   lc = -1;
    float row[9];
    if (tid < CHUNK) {
        const int s = chunk * CHUNK + tid;
        const int mval = mask[batch * Sn + s];
        lc = (mval > 0) ? s : -1;
        const bool act = (s >= 1) && (mval > 0);
        if (act) {
            #pragma unroll
            for (int i = 0; i < 3; i++)
                #pragma unroll
                for (int j = 0; j < 3; j++)
                    row[i * 3 + j] = str[i * 3 + j] + em[tid][j];
        } else {
            #pragma unroll
            for (int e = 0; e < 9; e++)
                row[e] = (e == 0 || e == 4 || e == 8) ? 0.0f : -1e30f;
        }
        if (s >= 1) {
            int lg = labels[batch * Sn + s];     int tg = lg < 0 ? 0 : lg;
            int lp = labels[batch * Sn + s - 1]; int tp = lp < 0 ? 0 : lp;
            float m = (mval > 0) ? 1.0f : 0.0f;
            gp = (em[tid][tg] + str[tp * 3 + tg]) * m;
        }
    }
    if (chunk == 0 && tid < 3)
        g_alpha0[batch][tid] = start[tid] + em[0][tid];

    // ---- in-warp ordered log-semiring allgather-reduce (warps 0,1)
    if (wid < 2) {
        #pragma unroll
        for (int l = 0; l < 5; l++) {
            float oth[9];
            #pragma unroll
            for (int e = 0; e < 9; e++)
                oth[e] = __shfl_xor_sync(0xffffffffu, row[e], 1 << l);
            const bool left = ((lane >> l) & 1) == 0;
            float A[9], Bm[9];
            #pragma unroll
            for (int e = 0; e < 9; e++) {
                A[e]  = left ? row[e] : oth[e];
                Bm[e] = left ? oth[e] : row[e];
            }
            #pragma unroll
            for (int i = 0; i < 3; i++)
                #pragma unroll
                for (int k = 0; k < 3; k++)
                    row[i * 3 + k] = lse3(A[i * 3 + 0] + Bm[0 + k],
                                          A[i * 3 + 1] + Bm[3 + k],
                                          A[i * 3 + 2] + Bm[6 + k]);
        }
        #pragma unroll
        for (int off = 16; off; off >>= 1) {
            gp += __shfl_xor_sync(0xffffffffu, gp, off);
            lc  = max(lc, __shfl_xor_sync(0xffffffffu, lc, off));
        }
        if (lane < 9) wprod[wid][lane] = row[lane];
        if (lane == 0) { sgold[wid] = gp; slast[wid] = lc; }
    }
    __syncthreads();

    if (tid < 9) {
        const int i = tid / 3, k = tid - i * 3;
        g_M[batch][chunk][tid] = lse3(wprod[0][i * 3 + 0] + wprod[1][0 + k],
                                      wprod[0][i * 3 + 1] + wprod[1][3 + k],
                                      wprod[0][i * 3 + 2] + wprod[1][6 + k]);
    }
    if (tid == 0) {
        g_gold[batch][chunk] = sgold[0] + sgold[1];
        g_last[batch][chunk] = max(slast[0], slast[1]);
    }

    // ==== last-block-done epilogue ====
    __threadfence();
    if (tid == 0) {
        unsigned int n = atomicAdd(&g_ctr, 1u);
        s_is_last = (n == (unsigned)(NCH * Bn - 1)) ? 1 : 0;
    }
    __syncthreads();
    if (!s_is_last) return;
    if (tid == 0) g_ctr = 0;   // reset for next graph replay

    float val = 0.0f;
    if (tid < Bn) {
        const int b = tid;
        float M[9];
        #pragma unroll
        for (int e = 0; e < 9; e++) M[e] = __ldcg(&g_M[b][0][e]);
        #pragma unroll
        for (int c = 1; c < NCH; c++) {
            float Nm[9], R[9];
            #pragma unroll
            for (int e = 0; e < 9; e++) Nm[e] = __ldcg(&g_M[b][c][e]);
            #pragma unroll
            for (int i = 0; i < 3; i++)
                #pragma unroll
                for (int k = 0; k < 3; k++)
                    R[i * 3 + k] = lse3(M[i * 3 + 0] + Nm[0 + k],
                                        M[i * 3 + 1] + Nm[3 + k],
                                        M[i * 3 + 2] + Nm[6 + k]);
            #pragma unroll
            for (int e = 0; e < 9; e++) M[e] = R[e];
        }

        int last = 0;
        #pragma unroll
        for (int c = 0; c < NCH; c++) last = max(last, __ldcg(&g_last[b][c]));

        float al0 = __ldcg(&g_alpha0[b][0]);
        float al1 = __ldcg(&g_alpha0[b][1]);
        float al2 = __ldcg(&g_alpha0[b][2]);
        float af0 = lse3(al0 + M[0], al1 + M[3], al2 + M[6]);
        float af1 = lse3(al0 + M[1], al1 + M[4], al2 + M[7]);
        float af2 = lse3(al0 + M[2], al1 + M[5], al2 + M[8]);
        float e0 = endt[0], e1 = endt[1], e2 = endt[2];
        float logz = lse3(af0 + e0, af1 + e1, af2 + e2);

        int l0 = labels[(size_t)b * Sn];        int t0 = l0 < 0 ? 0 : l0;
        int ll = labels[(size_t)b * Sn + last]; int lt = ll < 0 ? 0 : ll;
        float et = (lt == 0) ? e0 : ((lt == 1) ? e1 : e2);
        float a0 = (t0 == 0) ? al0 : ((t0 == 1) ? al1 : al2);
        float score = a0 + et;
        #pragma unroll
        for (int c = 0; c < NCH; c++) score += __ldcg(&g_gold[b][c]);
        val = score - logz;
    }

    if (wid < 2) {
        #pragma unroll
        for (int off = 16; off; off >>= 1)
            val += __shfl_xor_sync(0xffffffffu, val, off);
        if (lane == 0) sred[wid] = val;
    }
    __syncthreads();
    if (tid == 0) out[0] = -(sred[0] + sred[1]) * (1.0f / 64.0f);
}

extern "C" void kernel_launch(void* const* d_in, const int* in_sizes, int n_in,
                              void* d_out, int out_size) {
    const float* hidden = (const float*)d_in[0];
    const float* W      = (const float*)d_in[1];
    const float* bias   = (const float*)d_in[2];
    const float* start  = (const float*)d_in[3];
    const float* endt   = (const float*)d_in[4];
    const float* trans  = (const float*)d_in[5];
    const int*   mask   = (const int*)d_in[6];
    const int*   labels = (const int*)d_in[7];

    crf_fused<<<dim3(NCH, Bn), T1>>>(hidden, W, bias, start, endt, trans,
                                     mask, labels, (float*)d_out);
}

// round 6
// speedup vs baseline: 1.0597x; 1.0597x over previous
#include <cuda_runtime.h>

// CRF token-classifier NLL, single fused kernel. B=64,S=512,H=768,L=3 -> scalar.
// Emission GEMV with 8-lane reduction mapping (lane = 8*tsub + e):
// 4 timesteps/warp, W LDS broadcast, 3-level shfl reduce. Register-resident
// shfl log-semiring 3x3 reduce; last-block-done epilogue.

#define Bn 64
#define Sn 512
#define Hn 768
#define CHUNK 64
#define NCH (Sn / CHUNK) // 8
#define T1 256

// scratch (no allocations allowed)
__device__ float g_M[Bn][NCH][9];
__device__ float g_gold[Bn][NCH];
__device__ float g_alpha0[Bn][3];
__device__ int   g_last[Bn][NCH];
__device__ unsigned int g_ctr = 0;

__device__ __forceinline__ float lse3(float a, float b, float c) {
    float m = fmaxf(a, fmaxf(b, c));
    return m + __logf(__expf(a - m) + __expf(b - m) + __expf(c - m));
}

__device__ __forceinline__ float dot4(float4 x, float4 v) {
    return x.x * v.x + x.y * v.y + x.z * v.z + x.w * v.w;
}

__global__ __launch_bounds__(T1, 5) void crf_fused(
    const float* __restrict__ hidden, const float* __restrict__ W,
    const float* __restrict__ bias, const float* __restrict__ start,
    const float* __restrict__ endt, const float* __restrict__ trans,
    const int* __restrict__ mask, const int* __restrict__ labels,
    float* __restrict__ out)
{
    const int chunk = blockIdx.x;
    const int batch = blockIdx.y;
    const int tid = threadIdx.x, lane = tid & 31, wid = tid >> 5;
    const int e8 = lane & 7, tsub = lane >> 3;

    __shared__ float w0[Hn], w1[Hn], w2[Hn];   // W transposed (9.2 KB)
    __shared__ float em[CHUNK][4];             // emissions
    __shared__ float str[9];
    __shared__ float wprod[2][9];
    __shared__ float sgold[2];
    __shared__ int   slast[2];
    __shared__ int   s_is_last;
    __shared__ float sred[2];

    // stage W (transposed) and transitions
    for (int i = tid; i < Hn; i += T1) {
        w0[i] = W[i * 3 + 0];
        w1[i] = W[i * 3 + 1];
        w2[i] = W[i * 3 + 2];
    }
    if (tid < 9) str[tid] = trans[tid];
    __syncthreads();

    const float* hb = hidden + ((size_t)batch * Sn + (size_t)chunk * CHUNK) * Hn;
    const float bb0 = bias[0], bb1 = bias[1], bb2 = bias[2];

    // ---- emissions: warp covers 4 timesteps (tsub) x 8-lane h-slices (e8).
    //      h = 4*e8 + 32*k, k = 0..23. Two passes of 32 timesteps.
    #pragma unroll
    for (int g = 0; g < 2; g++) {
        const int ts = g * 32 + wid * 4 + tsub;
        const float* xr = hb + (size_t)ts * Hn + 4 * e8;
        const float4* wp0 = (const float4*)(w0 + 4 * e8);
        const float4* wp1 = (const float4*)(w1 + 4 * e8);
        const float4* wp2 = (const float4*)(w2 + 4 * e8);

        float a0 = 0, a1 = 0, a2 = 0, b0 = 0, b1 = 0, b2 = 0;
        #pragma unroll
        for (int k = 0; k < 24; k += 2) {
            float4 xA = __ldcs((const float4*)(xr + 32 * k));
            float4 xB = __ldcs((const float4*)(xr + 32 * (k + 1)));
            float4 vA0 = wp0[8 * k],       vA1 = wp1[8 * k],       vA2 = wp2[8 * k];
            float4 vB0 = wp0[8 * (k + 1)], vB1 = wp1[8 * (k + 1)], vB2 = wp2[8 * (k + 1)];
            a0 += dot4(xA, vA0); a1 += dot4(xA, vA1); a2 += dot4(xA, vA2);
            b0 += dot4(xB, vB0); b1 += dot4(xB, vB1); b2 += dot4(xB, vB2);
        }
        a0 += b0; a1 += b1; a2 += b2;

        // 3-level reduce over the 8-lane group (xor 1,2,4 stays in-group)
        #pragma unroll
        for (int off = 1; off < 8; off <<= 1) {
            a0 += __shfl_xor_sync(0xffffffffu, a0, off);
            a1 += __shfl_xor_sync(0xffffffffu, a1, off);
            a2 += __shfl_xor_sync(0xffffffffu, a2, off);
        }
        if (e8 == 0) {
            em[ts][0] = a0 + bb0;
            em[ts][1] = a1 + bb1;
            em[ts][2] = a2 + bb2;
        }
    }
    __syncthreads();

    // ---- per-step matrices (registers) + gold partial + last-mask index
    float gp = 0.0f;
    int   lc = -1;
    float row[9];
    if (tid < CHUNK) {
        const int s = chunk * CHUNK + tid;
        const int mval = mask[batch * Sn + s];
        lc = (mval > 0) ? s : -1;
        const bool act = (s >= 1) && (mval > 0);
        if (act) {
            #pragma unroll
            for (int i = 0; i < 3; i++)
                #pragma unroll
                for (int j = 0; j < 3; j++)
                    row[i * 3 + j] = str[i * 3 + j] + em[tid][j];
        } else {
            #pragma unroll
            for (int e = 0; e < 9; e++)
                row[e] = (e == 0 || e == 4 || e == 8) ? 0.0f : -1e30f;
        }
        if (s >= 1) {
            int lg = labels[batch * Sn + s];     int tg = lg < 0 ? 0 : lg;
            int lp = labels[batch * Sn + s - 1]; int tp = lp < 0 ? 0 : lp;
            float m = (mval > 0) ? 1.0f : 0.0f;
            gp = (em[tid][tg] + str[tp * 3 + tg]) * m;
        }
    }
    if (chunk == 0 && tid < 3)
        g_alpha0[batch][tid] = start[tid] + em[0][tid];

    // ---- in-warp ordered log-semiring allgather-reduce (warps 0,1)
    if (wid < 2) {
        #pragma unroll
        for (int l = 0; l < 5; l++) {
            float oth[9];
            #pragma unroll
            for (int e = 0; e < 9; e++)
                oth[e] = __shfl_xor_sync(0xffffffffu, row[e], 1 << l);
            const bool left = ((lane >> l) & 1) == 0;
            float A[9], Bm[9];
            #pragma unroll
            for (int e = 0; e < 9; e++) {
                A[e]  = left ? row[e] : oth[e];
                Bm[e] = left ? oth[e] : row[e];
            }
            #pragma unroll
            for (int i = 0; i < 3; i++)
                #pragma unroll
                for (int k = 0; k < 3; k++)
                    row[i * 3 + k] = lse3(A[i * 3 + 0] + Bm[0 + k],
                                          A[i * 3 + 1] + Bm[3 + k],
                                          A[i * 3 + 2] + Bm[6 + k]);
        }
        #pragma unroll
        for (int off = 16; off; off >>= 1) {
            gp += __shfl_xor_sync(0xffffffffu, gp, off);
            lc  = max(lc, __shfl_xor_sync(0xffffffffu, lc, off));
        }
        if (lane < 9) wprod[wid][lane] = row[lane];
        if (lane == 0) { sgold[wid] = gp; slast[wid] = lc; }
    }
    __syncthreads();

    if (tid < 9) {
        const int i = tid / 3, k = tid - i * 3;
        g_M[batch][chunk][tid] = lse3(wprod[0][i * 3 + 0] + wprod[1][0 + k],
                                      wprod[0][i * 3 + 1] + wprod[1][3 + k],
                                      wprod[0][i * 3 + 2] + wprod[1][6 + k]);
    }
    if (tid == 0) {
        g_gold[batch][chunk] = sgold[0] + sgold[1];
        g_last[batch][chunk] = max(slast[0], slast[1]);
    }

    // ==== last-block-done epilogue ====
    __threadfence();
    if (tid == 0) {
        unsigned int n = atomicAdd(&g_ctr, 1u);
        s_is_last = (n == (unsigned)(NCH * Bn - 1)) ? 1 : 0;
    }
    __syncthreads();
    if (!s_is_last) return;
    if (tid == 0) g_ctr = 0;   // reset for next graph replay

    float val = 0.0f;
    if (tid < Bn) {
        const int b = tid;
        float M[9];
        #pragma unroll
        for (int e = 0; e < 9; e++) M[e] = __ldcg(&g_M[b][0][e]);
        #pragma unroll
        for (int c = 1; c < NCH; c++) {
            float Nm[9], R[9];
            #pragma unroll
            for (int e = 0; e < 9; e++) Nm[e] = __ldcg(&g_M[b][c][e]);
            #pragma unroll
            for (int i = 0; i < 3; i++)
                #pragma unroll
                for (int k = 0; k < 3; k++)
                    R[i * 3 + k] = lse3(M[i * 3 + 0] + Nm[0 + k],
                                        M[i * 3 + 1] + Nm[3 + k],
                                        M[i * 3 + 2] + Nm[6 + k]);
            #pragma unroll
            for (int e = 0; e < 9; e++) M[e] = R[e];
        }

        int last = 0;
        #pragma unroll
        for (int c = 0; c < NCH; c++) last = max(last, __ldcg(&g_last[b][c]));

        float al0 = __ldcg(&g_alpha0[b][0]);
        float al1 = __ldcg(&g_alpha0[b][1]);
        float al2 = __ldcg(&g_alpha0[b][2]);
        float af0 = lse3(al0 + M[0], al1 + M[3], al2 + M[6]);
        float af1 = lse3(al0 + M[1], al1 + M[4], al2 + M[7]);
        float af2 = lse3(al0 + M[2], al1 + M[5], al2 + M[8]);
        float e0 = endt[0], e1 = endt[1], e2 = endt[2];
        float logz = lse3(af0 + e0, af1 + e1, af2 + e2);

        int l0 = labels[(size_t)b * Sn];        int t0 = l0 < 0 ? 0 : l0;
        int ll = labels[(size_t)b * Sn + last]; int lt = ll < 0 ? 0 : ll;
        float et = (lt == 0) ? e0 : ((lt == 1) ? e1 : e2);
        float a0 = (t0 == 0) ? al0 : ((t0 == 1) ? al1 : al2);
        float score = a0 + et;
        #pragma unroll
        for (int c = 0; c < NCH; c++) score += __ldcg(&g_gold[b][c]);
        val = score - logz;
    }

    if (wid < 2) {
        #pragma unroll
        for (int off = 16; off; off >>= 1)
            val += __shfl_xor_sync(0xffffffffu, val, off);
        if (lane == 0) sred[wid] = val;
    }
    __syncthreads();
    if (tid == 0) out[0] = -(sred[0] + sred[1]) * (1.0f / 64.0f);
}

extern "C" void kernel_launch(void* const* d_in, const int* in_sizes, int n_in,
                              void* d_out, int out_size) {
    const float* hidden = (const float*)d_in[0];
    const float* W      = (const float*)d_in[1];
    const float* bias   = (const float*)d_in[2];
    const float* start  = (const float*)d_in[3];
    const float* endt   = (const float*)d_in[4];
    const float* trans  = (const float*)d_in[5];
    const int*   mask   = (const int*)d_in[6];
    const int*   labels = (const int*)d_in[7];

    crf_fused<<<dim3(NCH, Bn), T1>>>(hidden, W, bias, start, endt, trans,
                                     mask, labels, (float*)d_out);
}

// round 7
// speedup vs baseline: 1.2109x; 1.1427x over previous
#include <cuda_runtime.h>

// CRF token-classifier NLL, single fused kernel. B=64,S=512,H=768,L=3 -> scalar.
// R4 lane mapping (h = 4*lane + 128*k), but one fused 8-timestep pass per warp
// (24 accumulators, single reduction tail). CHUNK=32 / 128-thread blocks for
// grid balance; semiring scan = exactly one warp. Last-block-done epilogue.

#define Bn 64
#define Sn 512
#define Hn 768
#define CHUNK 32
#define NCH (Sn / CHUNK) // 16
#define T1 128           // 4 warps

// scratch (no allocations allowed)
__device__ float g_M[Bn][NCH][9];
__device__ float g_gold[Bn][NCH];
__device__ float g_alpha0[Bn][3];
__device__ int   g_last[Bn][NCH];
__device__ unsigned int g_ctr = 0;

__device__ __forceinline__ float lse3(float a, float b, float c) {
    float m = fmaxf(a, fmaxf(b, c));
    return m + __logf(__expf(a - m) + __expf(b - m) + __expf(c - m));
}

__device__ __forceinline__ float dot4(float4 x, float4 v) {
    return x.x * v.x + x.y * v.y + x.z * v.z + x.w * v.w;
}

__global__ __launch_bounds__(T1, 8) void crf_fused(
    const float* __restrict__ hidden, const float* __restrict__ W,
    const float* __restrict__ bias, const float* __restrict__ start,
    const float* __restrict__ endt, const float* __restrict__ trans,
    const int* __restrict__ mask, const int* __restrict__ labels,
    float* __restrict__ out)
{
    const int chunk = blockIdx.x;
    const int batch = blockIdx.y;
    const int tid = threadIdx.x, lane = tid & 31, wid = tid >> 5;

    __shared__ float w0[Hn], w1[Hn], w2[Hn];   // W transposed (9.2 KB)
    __shared__ float em[CHUNK][4];             // emissions
    __shared__ float str[9];
    __shared__ int   s_is_last;
    __shared__ float sred[2];

    // stage W (transposed) and transitions
    for (int i = tid; i < Hn; i += T1) {
        w0[i] = W[i * 3 + 0];
        w1[i] = W[i * 3 + 1];
        w2[i] = W[i * 3 + 2];
    }
    if (tid < 9) str[tid] = trans[tid];
    __syncthreads();

    const float* hb = hidden + ((size_t)batch * Sn + (size_t)chunk * CHUNK) * Hn;
    const float bb0 = bias[0], bb1 = bias[1], bb2 = bias[2];

    // ---- emissions: warp wid covers timesteps [8*wid, 8*wid+8).
    //      lane covers h = 4*lane + 128*k, k = 0..5. One fused pass:
    //      48 LDG.128 per thread-row issued across one FMA-shadowed phase.
    {
        const float* xr = hb + (size_t)(wid * 8) * Hn + 4 * lane;
        float acc[8][3];
        #pragma unroll
        for (int t = 0; t < 8; t++)
            #pragma unroll
            for (int j = 0; j < 3; j++) acc[t][j] = 0.0f;

        #pragma unroll
        for (int k = 0; k < 6; k++) {
            const int h = 4 * lane + 128 * k;
            float4 v0 = *(const float4*)(w0 + h);
            float4 v1 = *(const float4*)(w1 + h);
            float4 v2 = *(const float4*)(w2 + h);
            #pragma unroll
            for (int t = 0; t < 8; t++) {
                float4 x = __ldcs((const float4*)(xr + (size_t)t * Hn + 128 * k));
                acc[t][0] += dot4(x, v0);
                acc[t][1] += dot4(x, v1);
                acc[t][2] += dot4(x, v2);
            }
        }

        // single reduction tail: 5-level butterfly over 24 values
        #pragma unroll
        for (int off = 16; off; off >>= 1)
            #pragma unroll
            for (int t = 0; t < 8; t++)
                #pragma unroll
                for (int j = 0; j < 3; j++)
                    acc[t][j] += __shfl_xor_sync(0xffffffffu, acc[t][j], off);

        if (lane == 0) {
            #pragma unroll
            for (int t = 0; t < 8; t++) {
                em[wid * 8 + t][0] = acc[t][0] + bb0;
                em[wid * 8 + t][1] = acc[t][1] + bb1;
                em[wid * 8 + t][2] = acc[t][2] + bb2;
            }
        }
    }
    __syncthreads();

    // ---- warp 0: per-step matrices + ordered semiring allgather-reduce
    //      (32 steps == 32 lanes, no cross-warp combine needed)
    if (wid == 0) {
        const int s = chunk * CHUNK + lane;
        const int mval = mask[batch * Sn + s];
        int lc = (mval > 0) ? s : -1;
        const bool act = (s >= 1) && (mval > 0);
        float row[9];
        if (act) {
            #pragma unroll
            for (int i = 0; i < 3; i++)
                #pragma unroll
                for (int j = 0; j < 3; j++)
                    row[i * 3 + j] = str[i * 3 + j] + em[lane][j];
        } else {
            #pragma unroll
            for (int e = 0; e < 9; e++)
                row[e] = (e == 0 || e == 4 || e == 8) ? 0.0f : -1e30f;
        }
        float gp = 0.0f;
        if (s >= 1) {
            int lg = labels[batch * Sn + s];     int tg = lg < 0 ? 0 : lg;
            int lp = labels[batch * Sn + s - 1]; int tp = lp < 0 ? 0 : lp;
            float m = (mval > 0) ? 1.0f : 0.0f;
            gp = (em[lane][tg] + str[tp * 3 + tg]) * m;
        }
        if (chunk == 0 && lane < 3)
            g_alpha0[batch][lane] = start[lane] + em[0][lane];

        #pragma unroll
        for (int l = 0; l < 5; l++) {
            float oth[9];
            #pragma unroll
            for (int e = 0; e < 9; e++)
                oth[e] = __shfl_xor_sync(0xffffffffu, row[e], 1 << l);
            const bool left = ((lane >> l) & 1) == 0;
            float A[9], Bm[9];
            #pragma unroll
            for (int e = 0; e < 9; e++) {
                A[e]  = left ? row[e] : oth[e];
                Bm[e] = left ? oth[e] : row[e];
            }
            #pragma unroll
            for (int i = 0; i < 3; i++)
                #pragma unroll
                for (int k = 0; k < 3; k++)
                    row[i * 3 + k] = lse3(A[i * 3 + 0] + Bm[0 + k],
                                          A[i * 3 + 1] + Bm[3 + k],
                                          A[i * 3 + 2] + Bm[6 + k]);
        }
        #pragma unroll
        for (int off = 16; off; off >>= 1) {
            gp += __shfl_xor_sync(0xffffffffu, gp, off);
            lc  = max(lc, __shfl_xor_sync(0xffffffffu, lc, off));
        }
        if (lane == 0) {
            #pragma unroll
            for (int e = 0; e < 9; e++) g_M[batch][chunk][e] = row[e];
            g_gold[batch][chunk] = gp;
            g_last[batch][chunk] = lc;
        }
    }

    // ==== last-block-done epilogue ====
    __threadfence();
    __syncthreads();
    if (tid == 0) {
        unsigned int n = atomicAdd(&g_ctr, 1u);
        s_is_last = (n == (unsigned)(NCH * Bn - 1)) ? 1 : 0;
    }
    __syncthreads();
    if (!s_is_last) return;
    if (tid == 0) g_ctr = 0;   // reset for next graph replay

    float val = 0.0f;
    if (tid < Bn) {
        const int b = tid;
        float M[9];
        #pragma unroll
        for (int e = 0; e < 9; e++) M[e] = __ldcg(&g_M[b][0][e]);
        #pragma unroll
        for (int c = 1; c < NCH; c++) {
            float Nm[9], R[9];
            #pragma unroll
            for (int e = 0; e < 9; e++) Nm[e] = __ldcg(&g_M[b][c][e]);
            #pragma unroll
            for (int i = 0; i < 3; i++)
                #pragma unroll
                for (int k = 0; k < 3; k++)
                    R[i * 3 + k] = lse3(M[i * 3 + 0] + Nm[0 + k],
                                        M[i * 3 + 1] + Nm[3 + k],
                                        M[i * 3 + 2] + Nm[6 + k]);
            #pragma unroll
            for (int e = 0; e < 9; e++) M[e] = R[e];
        }

        int last = 0;
        #pragma unroll
        for (int c = 0; c < NCH; c++) last = max(last, __ldcg(&g_last[b][c]));

        float al0 = __ldcg(&g_alpha0[b][0]);
        float al1 = __ldcg(&g_alpha0[b][1]);
        float al2 = __ldcg(&g_alpha0[b][2]);
        float af0 = lse3(al0 + M[0], al1 + M[3], al2 + M[6]);
        float af1 = lse3(al0 + M[1], al1 + M[4], al2 + M[7]);
        float af2 = lse3(al0 + M[2], al1 + M[5], al2 + M[8]);
        float e0 = endt[0], e1 = endt[1], e2 = endt[2];
        float logz = lse3(af0 + e0, af1 + e1, af2 + e2);

        int l0 = labels[(size_t)b * Sn];        int t0 = l0 < 0 ? 0 : l0;
        int ll = labels[(size_t)b * Sn + last]; int lt = ll < 0 ? 0 : ll;
        float et = (lt == 0) ? e0 : ((lt == 1) ? e1 : e2);
        float a0 = (t0 == 0) ? al0 : ((t0 == 1) ? al1 : al2);
        float score = a0 + et;
        #pragma unroll
        for (int c = 0; c < NCH; c++) score += __ldcg(&g_gold[b][c]);
        val = score - logz;
    }

    if (wid < 2) {
        #pragma unroll
        for (int off = 16; off; off >>= 1)
            val += __shfl_xor_sync(0xffffffffu, val, off);
        if (lane == 0) sred[wid] = val;
    }
    __syncthreads();
    if (tid == 0) out[0] = -(sred[0] + sred[1]) * (1.0f / 64.0f);
}

extern "C" void kernel_launch(void* const* d_in, const int* in_sizes, int n_in,
                              void* d_out, int out_size) {
    const float* hidden = (const float*)d_in[0];
    const float* W      = (const float*)d_in[1];
    const float* bias   = (const float*)d_in[2];
    const float* start  = (const float*)d_in[3];
    const float* endt   = (const float*)d_in[4];
    const float* trans  = (const float*)d_in[5];
    const int*   mask   = (const int*)d_in[6];
    const int*   labels = (const int*)d_in[7];

    crf_fused<<<dim3(NCH, Bn), T1>>>(hidden, W, bias, start, endt, trans,
                                     mask, labels, (float*)d_out);
}